// round 2
// baseline (speedup 1.0000x reference)
#include <cuda_runtime.h>
#include <math.h>

// ---------------- problem constants ----------------
#define D      2048          // feature dim
#define LIDS   4000          // num identities (L)
#define CAMS   8             // num cameras (C)
#define MCENT  (LIDS*CAMS)   // 32000 centers
#define TINV   (1.0f/0.07f)  // 1/T
#define HARDK  50
#define NMAXS  256           // max batch size

// ---------------- GEMM tiling ----------------
#define TILE_M 32
#define TILE_N 128
#define TILE_K 32
#define NTILES 32            // ceil(4000/128): tiles 0..30 full, tile 31 has 32 cols

// ---------------- scratch (no allocation allowed) ----------------
__device__ __align__(16) float g_featsN[NMAXS * D];   // normalized feats * (1/T)
__device__ float g_partial[NMAXS * NTILES];           // per (sample, ntile) exp-sums (intra)
__device__ float g_own[NMAXS];                        // own logit per sample
__device__ float g_sum_inter[NMAXS];                  // inter denominator per sample
__device__ int   g_is64;                              // labels/camids stored as int64?

// read an index that may be int32 or int64
__device__ __forceinline__ int loadIdx(const void* p, int i) {
    if (g_is64) return (int)((const long long*)p)[i];
    return ((const int*)p)[i];
}

// ---------------- kernel 0: dtype detection ----------------
// int64 labels < 32000: every odd 32-bit word of the first n words is the zero
// high half. int32: odd words are random labels (nonzero with prob ~1).
__global__ void k_detect(const int* __restrict__ words, int n) {
    __shared__ int nz;
    if (threadIdx.x == 0) nz = 0;
    __syncthreads();
    for (int i = threadIdx.x; i < n; i += blockDim.x)
        if ((i & 1) && words[i] != 0) atomicOr(&nz, 1);
    __syncthreads();
    if (threadIdx.x == 0) g_is64 = (nz == 0) ? 1 : 0;
}

// ---------------- kernel 1: normalize feats, fold 1/T ----------------
__global__ void __launch_bounds__(256) k_norm(const float* __restrict__ feats) {
    const int i = blockIdx.x;
    const int t = threadIdx.x;
    __shared__ float red[256];
    const float* f = feats + (size_t)i * D;
    float s = 0.f;
    for (int k4 = t; k4 < D / 4; k4 += 256) {
        float4 v = *(const float4*)(f + 4 * k4);
        s += v.x * v.x + v.y * v.y + v.z * v.z + v.w * v.w;
    }
    red[t] = s;
    __syncthreads();
    for (int o = 128; o; o >>= 1) { if (t < o) red[t] += red[t + o]; __syncthreads(); }
    const float scale = TINV / sqrtf(red[0]);
    float* out = g_featsN + (size_t)i * D;
    for (int k4 = t; k4 < D / 4; k4 += 256) {
        float4 v = *(const float4*)(f + 4 * k4);
        v.x *= scale; v.y *= scale; v.z *= scale; v.w *= scale;
        *(float4*)(out + 4 * k4) = v;
    }
}

// ---------------- kernel 2: per-cam GEMM + exp row-sums (intra denominator) ---
// grid = (NTILES, 2 m-tiles, 8 cams), block = 256 threads.
// Samples of cam c (~32) x 128 centers with j%8==c; packed f32x2 FMA inner loop.
// fma-pipe bound: per kk bundle 16 FFMA2 (32 cyc) vs 10 other issue slots.
__global__ void __launch_bounds__(256) k_gemm(const float* __restrict__ centers,
                                              const void* __restrict__ camids, int n) {
    const int nt = blockIdx.x, mt = blockIdx.y, cam = blockIdx.z;
    const int t = threadIdx.x;

    __shared__ int   s_cam[NMAXS];
    __shared__ int   s_list[2 * TILE_M];
    __shared__ int   s_cnt;
    __shared__ __align__(16) float As[TILE_M][TILE_K + 1];   // 32 x 33, store conflict-free
    __shared__ __align__(16) float Bs[TILE_K][TILE_N + 2];   // 32 x 130, LDS.64 conflict-free

    if (t == 0) s_cnt = 0;
    if (t < n) s_cam[t] = loadIdx(camids, t);
    __syncthreads();
    if (t < n && s_cam[t] == cam) {
        int pos = 0;
        for (int j = 0; j < t; j++) pos += (s_cam[j] == cam);
        if (pos < 2 * TILE_M) s_list[pos] = t;
        atomicAdd(&s_cnt, 1);
    }
    __syncthreads();
    const int n_c = min(s_cnt, 2 * TILE_M);
    if (mt * TILE_M >= n_c) return;   // uniform across block (spill-tile early exit)

    const int tx = t & 31, ty = t >> 5;

    // A-load mapping: thread -> (row am, k-quad aj)
    const int am = t >> 3, aj = t & 7;
    const int lm_load = mt * TILE_M + am;
    const float* arow = (lm_load < n_c) ? (g_featsN + (size_t)s_list[lm_load] * D) : nullptr;
    // B-load mapping: thread -> (k-quad bj, base col bn0); covers 4 cols spaced 32
    const int bj = t & 7, bn0 = t >> 3;

    unsigned long long acc[4][2];
#pragma unroll
    for (int i = 0; i < 4; i++) { acc[i][0] = 0ull; acc[i][1] = 0ull; }

    for (int kc = 0; kc < D; kc += TILE_K) {
        // stage A (32x32)
        float4 av = make_float4(0.f, 0.f, 0.f, 0.f);
        if (arow) av = *(const float4*)(arow + kc + 4 * aj);
        As[am][4 * aj + 0] = av.x; As[am][4 * aj + 1] = av.y;
        As[am][4 * aj + 2] = av.z; As[am][4 * aj + 3] = av.w;
        // stage B (128x32, stored transposed [k][n]); coalesced 128B segments
#pragma unroll
        for (int r = 0; r < 4; r++) {
            const int nb  = bn0 + 32 * r;
            const int cig = nt * TILE_N + nb;              // center index within this cam
            float4 bv = make_float4(0.f, 0.f, 0.f, 0.f);
            if (cig < LIDS)
                bv = *(const float4*)(centers + (size_t)(8 * cig + cam) * D + kc + 4 * bj);
            Bs[4 * bj + 0][nb] = bv.x; Bs[4 * bj + 1][nb] = bv.y;
            Bs[4 * bj + 2][nb] = bv.z; Bs[4 * bj + 3][nb] = bv.w;
        }
        __syncthreads();
#pragma unroll
        for (int kk = 0; kk < TILE_K; kk++) {
            const unsigned long long b01 = *(const unsigned long long*)&Bs[kk][2 * tx];
            const unsigned long long b23 = *(const unsigned long long*)&Bs[kk][64 + 2 * tx];
#pragma unroll
            for (int i = 0; i < 4; i++) {
                const float a = As[ty + 8 * i][kk];           // warp-uniform broadcast
                unsigned long long a2;
                asm("mov.b64 %0, {%1, %1};" : "=l"(a2) : "r"(__float_as_uint(a)));
                asm("fma.rn.f32x2 %0, %1, %2, %0;" : "+l"(acc[i][0]) : "l"(a2), "l"(b01));
                asm("fma.rn.f32x2 %0, %1, %2, %0;" : "+l"(acc[i][1]) : "l"(a2), "l"(b23));
            }
        }
        __syncthreads();
    }

    // epilogue: per-row sum of exp over this block's 128 centers (masked past 4000)
#pragma unroll
    for (int i = 0; i < 4; i++) {
        const int lm = mt * TILE_M + ty + 8 * i;
        float2 p0 = *(float2*)&acc[i][0];
        float2 p1 = *(float2*)&acc[i][1];
        float rs = 0.f;
        const int c0 = nt * TILE_N + 2 * tx;
        const int c1 = nt * TILE_N + 64 + 2 * tx;
        if (c0     < LIDS) rs += expf(p0.x);
        if (c0 + 1 < LIDS) rs += expf(p0.y);
        if (c1     < LIDS) rs += expf(p1.x);
        if (c1 + 1 < LIDS) rs += expf(p1.y);
        for (int o = 16; o; o >>= 1) rs += __shfl_xor_sync(0xFFFFFFFFu, rs, o);
        if (tx == 0 && lm < n_c)
            g_partial[s_list[lm] * NTILES + nt] = rs;
    }
}

// ---------------- kernel 3: inter denominator + own logit ----------------
// One block per sample; 8 warps cover 8 same-label centers + first 50 hard negs.
// Hard-neg rows are a subset of bank rows 0..57 -> L2-resident across samples.
__global__ void __launch_bounds__(256) k_inter(const float* __restrict__ centers,
                                               const void* __restrict__ labels,
                                               const void* __restrict__ camids) {
    const int i = blockIdx.x;
    const int t = threadIdx.x;
    __shared__ __align__(16) float sf[D];
    __shared__ float wsumS[8];
    const float* f = g_featsN + (size_t)i * D;
    for (int k4 = t; k4 < D / 4; k4 += 256)
        *(float4*)&sf[4 * k4] = *(const float4*)&f[4 * k4];
    const int lbl = loadIdx(labels, i);
    const int cam = loadIdx(camids, i);
    __syncthreads();

    const int w = t >> 5, lane = t & 31;
    float wsum = 0.f;
    for (int u = w; u < CAMS + HARDK; u += 8) {
        int j;
        if (u < CAMS) j = CAMS * lbl + u;                 // same-label centers (incl. own)
        else { const int m = u - CAMS; j = (m < CAMS * lbl) ? m : m + CAMS; }  // first-50 hard negs by index
        const float* crow = centers + (size_t)j * D;
        float d0 = 0.f, d1 = 0.f, d2 = 0.f, d3 = 0.f;
        for (int k4 = lane; k4 < D / 4; k4 += 32) {
            float4 c = *(const float4*)&crow[4 * k4];
            float4 a = *(const float4*)&sf[4 * k4];
            d0 += a.x * c.x; d1 += a.y * c.y; d2 += a.z * c.z; d3 += a.w * c.w;
        }
        float s = (d0 + d1) + (d2 + d3);
        for (int o = 16; o; o >>= 1) s += __shfl_xor_sync(0xFFFFFFFFu, s, o);
        wsum += expf(s);
        if (u < CAMS && u == cam && lane == 0) g_own[i] = s;   // own logit
    }
    if (lane == 0) wsumS[w] = wsum;
    __syncthreads();
    if (t == 0) {
        float tot = 0.f;
        for (int w2 = 0; w2 < 8; w2++) tot += wsumS[w2];   // fixed order: deterministic
        g_sum_inter[i] = tot;
    }
}

// ---------------- kernel 4: finalize ----------------
// sum over groups of per-group means == sum_i loss_i / cnt(group of i)
__global__ void __launch_bounds__(256) k_final(const void* __restrict__ labels,
                                               const void* __restrict__ camids,
                                               int n, float* __restrict__ out, int out_size) {
    __shared__ int sl[NMAXS], sc[NMAXS];
    __shared__ double rA[256], rB[256];
    const int t = threadIdx.x;
    if (t < n) { sl[t] = loadIdx(labels, t); sc[t] = loadIdx(camids, t); }
    __syncthreads();
    double a = 0.0, b = 0.0;
    if (t < n) {
        float sumI = 0.f;
        for (int nt = 0; nt < NTILES; nt++) sumI += g_partial[t * NTILES + nt];
        const float own = g_own[t];
        const float li = own - logf(sumI);
        const float lj = own - logf(g_sum_inter[t]);
        int cc = 0, cl = 0;
        for (int j = 0; j < n; j++) { cc += (sc[j] == sc[t]); cl += (sl[j] == sl[t]); }
        a = (double)li / (double)cc;
        b = (double)lj / (double)cl;
    }
    rA[t] = a; rB[t] = b;
    __syncthreads();
    for (int s = 128; s; s >>= 1) {
        if (t < s) { rA[t] += rA[t + s]; rB[t] += rB[t + s]; }
        __syncthreads();
    }
    if (t == 0) {
        out[0] = (float)(-rA[0]);                            // loss_intra
        if (out_size > 1) out[1] = (float)(0.5 * (-rB[0]));  // LAMDA * loss_inter
    }
}

// ---------------- launch ----------------
extern "C" void kernel_launch(void* const* d_in, const int* in_sizes, int n_in,
                              void* d_out, int out_size) {
    const float* feats   = (const float*)d_in[0];
    const float* centers = (const float*)d_in[1];
    const void*  labels  = d_in[2];
    const void*  camids  = d_in[3];
    // epoch (d_in[4] if present) unused: out_size encodes the static branch

    const int d = in_sizes[1] / MCENT;   // 2048
    const int n = in_sizes[0] / d;       // 256
    (void)n_in;

    k_detect<<<1, 256>>>((const int*)labels, n);
    k_norm<<<n, 256>>>(feats);
    dim3 g(NTILES, 2, CAMS);
    k_gemm<<<g, 256>>>(centers, camids, n);
    k_inter<<<n, 256>>>(centers, labels, camids);
    k_final<<<1, 256>>>(labels, camids, n, (float*)d_out, out_size);
}

// round 4
// speedup vs baseline: 1.1994x; 1.1994x over previous
#include <cuda_runtime.h>
#include <math.h>

// ---------------- problem constants ----------------
#define D      2048
#define LIDS   4000
#define CAMS   8
#define MCENT  (LIDS*CAMS)
#define TINV   (1.0f/0.07f)
#define NMAXS  256

// ---------------- GEMM tiling ----------------
#define TM     32
#define TN     256
#define TK     32
#define NT2    16            // ceil(4000/256) tiles; last tile masked
#define MT_CAP 2             // up to 64 samples per cam

typedef unsigned long long ull;

// ---------------- scratch (no allocation allowed) ----------------
__device__ __align__(16) float g_featsN[NMAXS * D];   // normalized feats * (1/T)
__device__ float g_partial[NMAXS * NT2];              // per (sample, ntile) intra exp-sums
__device__ float g_own[NMAXS];                        // own logit
__device__ float g_same[NMAXS];                       // sum exp over 8 same-label centers
__device__ float g_smallP[4 * NMAXS * 64];            // split-K partial sims vs bank rows 0..63
__device__ int   g_is64;

__device__ __forceinline__ int loadIdx(const void* p, int i) {
    if (g_is64) return (int)((const long long*)p)[i];
    return ((const int*)p)[i];
}

// ---------------- kernel 0: int32/int64 detection ----------------
// int64 values < 32000 => odd 32-bit words are all zero; int32 random labels => not.
__global__ void k_detect(const int* __restrict__ words, int n) {
    __shared__ int nz;
    if (threadIdx.x == 0) nz = 0;
    __syncthreads();
    for (int i = threadIdx.x; i < n; i += blockDim.x)
        if ((i & 1) && words[i] != 0) atomicOr(&nz, 1);
    __syncthreads();
    if (threadIdx.x == 0) g_is64 = (nz == 0) ? 1 : 0;
}

// ---------------- kernel 1: normalize feats, fold 1/T ----------------
__global__ void __launch_bounds__(256) k_norm(const float* __restrict__ feats) {
    const int i = blockIdx.x, t = threadIdx.x;
    __shared__ float red[256];
    const float* f = feats + (size_t)i * D;
    float s = 0.f;
    for (int k4 = t; k4 < D / 4; k4 += 256) {
        float4 v = *(const float4*)(f + 4 * k4);
        s += v.x * v.x + v.y * v.y + v.z * v.z + v.w * v.w;
    }
    red[t] = s;
    __syncthreads();
    for (int o = 128; o; o >>= 1) { if (t < o) red[t] += red[t + o]; __syncthreads(); }
    const float scale = TINV / sqrtf(red[0]);
    float* out = g_featsN + (size_t)i * D;
    for (int k4 = t; k4 < D / 4; k4 += 256) {
        float4 v = *(const float4*)(f + 4 * k4);
        v.x *= scale; v.y *= scale; v.z *= scale; v.w *= scale;
        *(float4*)(out + 4 * k4) = v;
    }
}

// ---------------- kernel 2: per-cam GEMM + intra exp row-sums ----------------
// grid (NT2, MT_CAP, 8 cams), block 256 = 8 warps.
// Warp w owns rows m=4w..4w+3; lane tx owns col pairs (2tx+64p), p=0..3.
// Register double-buffered global loads; A duplicated {a,a} so the FFMA2
// a-operand comes from one broadcast LDS.128 (no mov.b64 splat).
__global__ void __launch_bounds__(256) k_gemm(const float* __restrict__ centers,
                                              const void* __restrict__ camids, int n) {
    const int nt = blockIdx.x, mt = blockIdx.y, cam = blockIdx.z;
    const int t = threadIdx.x;

    __shared__ int   s_cam[NMAXS];
    __shared__ int   s_list[MT_CAP * TM];
    __shared__ int   s_cnt;
    __shared__ __align__(16) float2 AsP[TK * 34];   // [k][m] dup pairs, stride 34
    __shared__ __align__(16) float  Bs[TK * 258];   // [k][n], stride 258 (LDS.64 conflict-free)

    if (t == 0) s_cnt = 0;
    if (t < n) s_cam[t] = loadIdx(camids, t);
    __syncthreads();
    if (t < n && s_cam[t] == cam) {
        int pos = 0;
        for (int j = 0; j < t; j++) pos += (s_cam[j] == cam);
        if (pos < MT_CAP * TM) s_list[pos] = t;
        atomicAdd(&s_cnt, 1);
    }
    __syncthreads();
    const int n_c = min(s_cnt, MT_CAP * TM);
    if (mt * TM >= n_c) return;   // uniform across block (spill-tile early exit)

    const int tx = t & 31, w = t >> 5;
    // A loader: thread -> (row am, k-quad aj)
    const int am = t >> 3, aj = t & 7;
    const int lmA = mt * TM + am;
    const float* arow = (lmA < n_c) ? (g_featsN + (size_t)s_list[lmA] * D) : nullptr;
    // B loader: thread -> (k-quad bj, cols bn0+32r)
    const int bj = t & 7, bn0 = t >> 3;

    float4 av; float4 bv[8];
    av = arow ? *(const float4*)(arow + 4 * aj) : make_float4(0.f, 0.f, 0.f, 0.f);
#pragma unroll
    for (int r = 0; r < 8; r++) {
        const int cig = nt * TN + bn0 + 32 * r;
        bv[r] = (cig < LIDS) ? *(const float4*)(centers + (size_t)(8 * cig + cam) * D + 4 * bj)
                             : make_float4(0.f, 0.f, 0.f, 0.f);
    }

    ull acc[4][4];
#pragma unroll
    for (int i = 0; i < 4; i++)
#pragma unroll
        for (int p = 0; p < 4; p++) acc[i][p] = 0ull;

    for (int kc = 0; kc < D / TK; kc++) {
        AsP[(4 * aj + 0) * 34 + am] = make_float2(av.x, av.x);
        AsP[(4 * aj + 1) * 34 + am] = make_float2(av.y, av.y);
        AsP[(4 * aj + 2) * 34 + am] = make_float2(av.z, av.z);
        AsP[(4 * aj + 3) * 34 + am] = make_float2(av.w, av.w);
#pragma unroll
        for (int r = 0; r < 8; r++) {
            const int nb = bn0 + 32 * r;
            Bs[(4 * bj + 0) * 258 + nb] = bv[r].x;
            Bs[(4 * bj + 1) * 258 + nb] = bv[r].y;
            Bs[(4 * bj + 2) * 258 + nb] = bv[r].z;
            Bs[(4 * bj + 3) * 258 + nb] = bv[r].w;
        }
        __syncthreads();
        if (kc + 1 < D / TK) {                   // prefetch next tile under the kk-loop
            const int ko = (kc + 1) * TK;
            av = arow ? *(const float4*)(arow + ko + 4 * aj) : make_float4(0.f, 0.f, 0.f, 0.f);
#pragma unroll
            for (int r = 0; r < 8; r++) {
                const int cig = nt * TN + bn0 + 32 * r;
                bv[r] = (cig < LIDS) ? *(const float4*)(centers + (size_t)(8 * cig + cam) * D + ko + 4 * bj)
                                     : make_float4(0.f, 0.f, 0.f, 0.f);
            }
        }
#pragma unroll
        for (int kk = 0; kk < TK; kk++) {
            ulonglong2 a0 = *(const ulonglong2*)&AsP[kk * 34 + 4 * w];      // m=4w,4w+1 (bcast)
            ulonglong2 a1 = *(const ulonglong2*)&AsP[kk * 34 + 4 * w + 2];  // m=4w+2,4w+3
            ull A0 = a0.x, A1 = a0.y, A2 = a1.x, A3 = a1.y;
            ull b0 = *(const ull*)&Bs[kk * 258 + 2 * tx];
            ull b1 = *(const ull*)&Bs[kk * 258 + 2 * tx + 64];
            ull b2 = *(const ull*)&Bs[kk * 258 + 2 * tx + 128];
            ull b3 = *(const ull*)&Bs[kk * 258 + 2 * tx + 192];
            asm("fma.rn.f32x2 %0, %1, %2, %0;" : "+l"(acc[0][0]) : "l"(A0), "l"(b0));
            asm("fma.rn.f32x2 %0, %1, %2, %0;" : "+l"(acc[0][1]) : "l"(A0), "l"(b1));
            asm("fma.rn.f32x2 %0, %1, %2, %0;" : "+l"(acc[0][2]) : "l"(A0), "l"(b2));
            asm("fma.rn.f32x2 %0, %1, %2, %0;" : "+l"(acc[0][3]) : "l"(A0), "l"(b3));
            asm("fma.rn.f32x2 %0, %1, %2, %0;" : "+l"(acc[1][0]) : "l"(A1), "l"(b0));
            asm("fma.rn.f32x2 %0, %1, %2, %0;" : "+l"(acc[1][1]) : "l"(A1), "l"(b1));
            asm("fma.rn.f32x2 %0, %1, %2, %0;" : "+l"(acc[1][2]) : "l"(A1), "l"(b2));
            asm("fma.rn.f32x2 %0, %1, %2, %0;" : "+l"(acc[1][3]) : "l"(A1), "l"(b3));
            asm("fma.rn.f32x2 %0, %1, %2, %0;" : "+l"(acc[2][0]) : "l"(A2), "l"(b0));
            asm("fma.rn.f32x2 %0, %1, %2, %0;" : "+l"(acc[2][1]) : "l"(A2), "l"(b1));
            asm("fma.rn.f32x2 %0, %1, %2, %0;" : "+l"(acc[2][2]) : "l"(A2), "l"(b2));
            asm("fma.rn.f32x2 %0, %1, %2, %0;" : "+l"(acc[2][3]) : "l"(A2), "l"(b3));
            asm("fma.rn.f32x2 %0, %1, %2, %0;" : "+l"(acc[3][0]) : "l"(A3), "l"(b0));
            asm("fma.rn.f32x2 %0, %1, %2, %0;" : "+l"(acc[3][1]) : "l"(A3), "l"(b1));
            asm("fma.rn.f32x2 %0, %1, %2, %0;" : "+l"(acc[3][2]) : "l"(A3), "l"(b2));
            asm("fma.rn.f32x2 %0, %1, %2, %0;" : "+l"(acc[3][3]) : "l"(A3), "l"(b3));
        }
        __syncthreads();
    }

    // epilogue: per-row exp-sum over this tile's 256 cols (masked >= 4000)
#pragma unroll
    for (int i = 0; i < 4; i++) {
        const int lm = mt * TM + 4 * w + i;
        float rs = 0.f;
#pragma unroll
        for (int p = 0; p < 4; p++) {
            float2 v = *(float2*)&acc[i][p];
            const int c = nt * TN + 64 * p + 2 * tx;
            if (c     < LIDS) rs += expf(v.x);
            if (c + 1 < LIDS) rs += expf(v.y);
        }
        for (int o = 16; o; o >>= 1) rs += __shfl_xor_sync(0xFFFFFFFFu, rs, o);
        if (tx == 0 && lm < n_c) g_partial[s_list[lm] * NT2 + nt] = rs;
    }
}

// ---------------- kernel 3: small GEMM vs bank rows 0..63 (hard negatives) ----
// All first-50 hard negatives live in rows 0..57. Split-K (4 slices of 512)
// for parallelism; raw sims written exclusively per (slice, sample, col).
__global__ void __launch_bounds__(256) k_small(const float* __restrict__ centers, int n) {
    const int mt = blockIdx.x, ks = blockIdx.y;
    const int t = threadIdx.x;
    __shared__ __align__(16) float2 AsP[TK * 34];
    __shared__ __align__(16) float  Bs[TK * 66];

    const int tx = t & 31, w = t >> 5;
    const int am = t >> 3, aj = t & 7;
    const int row = mt * 32 + am;
    const float* arow = (row < n) ? (g_featsN + (size_t)row * D) : nullptr;
    const int bj = t & 7, bc0 = t >> 3;          // cols bc0, bc0+32
    const int kbase = ks * (D / 4);              // 512 k per slice

    float4 av, bv0, bv1;
    av  = arow ? *(const float4*)(arow + kbase + 4 * aj) : make_float4(0.f, 0.f, 0.f, 0.f);
    bv0 = *(const float4*)(centers + (size_t)bc0        * D + kbase + 4 * bj);
    bv1 = *(const float4*)(centers + (size_t)(bc0 + 32) * D + kbase + 4 * bj);

    ull acc[4] = {0ull, 0ull, 0ull, 0ull};

    for (int kc = 0; kc < (D / 4) / TK; kc++) {  // 16 tiles of 32
        AsP[(4 * aj + 0) * 34 + am] = make_float2(av.x, av.x);
        AsP[(4 * aj + 1) * 34 + am] = make_float2(av.y, av.y);
        AsP[(4 * aj + 2) * 34 + am] = make_float2(av.z, av.z);
        AsP[(4 * aj + 3) * 34 + am] = make_float2(av.w, av.w);
        Bs[(4 * bj + 0) * 66 + bc0] = bv0.x; Bs[(4 * bj + 1) * 66 + bc0] = bv0.y;
        Bs[(4 * bj + 2) * 66 + bc0] = bv0.z; Bs[(4 * bj + 3) * 66 + bc0] = bv0.w;
        Bs[(4 * bj + 0) * 66 + bc0 + 32] = bv1.x; Bs[(4 * bj + 1) * 66 + bc0 + 32] = bv1.y;
        Bs[(4 * bj + 2) * 66 + bc0 + 32] = bv1.z; Bs[(4 * bj + 3) * 66 + bc0 + 32] = bv1.w;
        __syncthreads();
        if (kc + 1 < (D / 4) / TK) {
            const int ko = kbase + (kc + 1) * TK;
            av  = arow ? *(const float4*)(arow + ko + 4 * aj) : make_float4(0.f, 0.f, 0.f, 0.f);
            bv0 = *(const float4*)(centers + (size_t)bc0        * D + ko + 4 * bj);
            bv1 = *(const float4*)(centers + (size_t)(bc0 + 32) * D + ko + 4 * bj);
        }
#pragma unroll
        for (int kk = 0; kk < TK; kk++) {
            ulonglong2 a0 = *(const ulonglong2*)&AsP[kk * 34 + 4 * w];
            ulonglong2 a1 = *(const ulonglong2*)&AsP[kk * 34 + 4 * w + 2];
            ull b0 = *(const ull*)&Bs[kk * 66 + 2 * tx];
            asm("fma.rn.f32x2 %0, %1, %2, %0;" : "+l"(acc[0]) : "l"(a0.x), "l"(b0));
            asm("fma.rn.f32x2 %0, %1, %2, %0;" : "+l"(acc[1]) : "l"(a0.y), "l"(b0));
            asm("fma.rn.f32x2 %0, %1, %2, %0;" : "+l"(acc[2]) : "l"(a1.x), "l"(b0));
            asm("fma.rn.f32x2 %0, %1, %2, %0;" : "+l"(acc[3]) : "l"(a1.y), "l"(b0));
        }
        __syncthreads();
    }
#pragma unroll
    for (int i = 0; i < 4; i++) {
        const int m = mt * 32 + 4 * w + i;
        if (m < n) *(float2*)&g_smallP[((size_t)ks * NMAXS + m) * 64 + 2 * tx] = *(float2*)&acc[i];
    }
}

// ---------------- kernel 4: same-label centers + own logit ----------------
// One block per sample; warp w handles center row 8*lbl+w (one pass, concurrent).
__global__ void __launch_bounds__(256) k_pair(const float* __restrict__ centers,
                                              const void* __restrict__ labels,
                                              const void* __restrict__ camids) {
    const int i = blockIdx.x, t = threadIdx.x;
    __shared__ __align__(16) float sf[D];
    __shared__ float wexp[8], wlog[8];
    const float* f = g_featsN + (size_t)i * D;
    for (int k4 = t; k4 < D / 4; k4 += 256)
        *(float4*)&sf[4 * k4] = *(const float4*)&f[4 * k4];
    const int lbl = loadIdx(labels, i), cam = loadIdx(camids, i);
    __syncthreads();

    const int w = t >> 5, lane = t & 31;
    const float* crow = centers + (size_t)(8 * lbl + w) * D;
    float d0 = 0.f, d1 = 0.f, d2 = 0.f, d3 = 0.f;
    for (int k4 = lane; k4 < D / 4; k4 += 32) {
        float4 c = *(const float4*)&crow[4 * k4];
        float4 a = *(const float4*)&sf[4 * k4];
        d0 += a.x * c.x; d1 += a.y * c.y; d2 += a.z * c.z; d3 += a.w * c.w;
    }
    float s = (d0 + d1) + (d2 + d3);
    for (int o = 16; o; o >>= 1) s += __shfl_xor_sync(0xFFFFFFFFu, s, o);
    if (lane == 0) { wexp[w] = expf(s); wlog[w] = s; }
    __syncthreads();
    if (t == 0) {
        float tot = 0.f;
        for (int q = 0; q < 8; q++) tot += wexp[q];   // fixed order: deterministic
        g_same[i] = tot;
        g_own[i]  = wlog[cam];
    }
}

// ---------------- kernel 5: finalize ----------------
// sum over groups of per-group means == sum_i loss_i / cnt(group of i)
__global__ void __launch_bounds__(256) k_final(const void* __restrict__ labels,
                                               const void* __restrict__ camids,
                                               int n, float* __restrict__ out, int out_size) {
    __shared__ int sl[NMAXS], sc[NMAXS];
    __shared__ double rA[256], rB[256];
    const int t = threadIdx.x;
    if (t < n) { sl[t] = loadIdx(labels, t); sc[t] = loadIdx(camids, t); }
    __syncthreads();
    double a = 0.0, b = 0.0;
    if (t < n) {
        float sumI = 0.f;
        for (int nt = 0; nt < NT2; nt++) sumI += g_partial[t * NT2 + nt];
        const float own = g_own[t];
        const int   l   = sl[t];
        float dj = g_same[t];
        for (int m = 0; m < 50; m++) {                  // first-50 hard negs by bank index
            const int j = (m < 8 * l) ? m : m + 8;      // j in [0,57]
            float s4 = 0.f;
            for (int ks = 0; ks < 4; ks++) s4 += g_smallP[((size_t)ks * NMAXS + t) * 64 + j];
            dj += expf(s4);
        }
        const float li = own - logf(sumI);
        const float lj = own - logf(dj);
        int cc = 0, cl = 0;
        for (int j = 0; j < n; j++) { cc += (sc[j] == sc[t]); cl += (sl[j] == sl[t]); }
        a = (double)li / (double)cc;
        b = (double)lj / (double)cl;
    }
    rA[t] = a; rB[t] = b;
    __syncthreads();
    for (int s = 128; s; s >>= 1) {
        if (t < s) { rA[t] += rA[t + s]; rB[t] += rB[t + s]; }
        __syncthreads();
    }
    if (t == 0) {
        out[0] = (float)(-rA[0]);
        if (out_size > 1) out[1] = (float)(0.5 * (-rB[0]));
    }
}

// ---------------- launch ----------------
extern "C" void kernel_launch(void* const* d_in, const int* in_sizes, int n_in,
                              void* d_out, int out_size) {
    const float* feats   = (const float*)d_in[0];
    const float* centers = (const float*)d_in[1];
    const void*  labels  = d_in[2];
    const void*  camids  = d_in[3];
    const int d = in_sizes[1] / MCENT;   // 2048
    const int n = in_sizes[0] / d;       // 256
    (void)n_in;

    k_detect<<<1, 256>>>((const int*)labels, n);
    k_norm<<<n, 256>>>(feats);
    dim3 gg(NT2, MT_CAP, CAMS);
    k_gemm<<<gg, 256>>>(centers, camids, n);
    dim3 gs((n + 31) / 32, 4);
    k_small<<<gs, 256>>>(centers, n);
    k_pair<<<n, 256>>>(centers, labels, camids);
    k_final<<<1, 256>>>(labels, camids, n, (float*)d_out, out_size);
}